// round 9
// baseline (speedup 1.0000x reference)
#include <cuda_runtime.h>
#include <cuda_bf16.h>
#include <cstdint>

// ============================================================================
// T=1, h0=c0=0 => w_hh* unused, f-gate unused. Chain of small GEMMs on HMMA
// (mma.sync m16n8k16 bf16). bf16x3: A segs [hi,hi,lo] vs W segs [Whi,Wlo,Whi].
// R9 (on top of R8's 16-warp streaming structure):
//  - weight image v2: i,g fragments interleaved (LDS.128), o separate (LDS.64)
//  - epilogue algebra in packed f32x2 (fma2 only; proven on compute_103)
//  - bf16x2 packing via __float22bfloat162_rn (1 instr per pair)
// Persistent: 148 CTAs x 512 thr; warp owns 32 rows, warp-private A smem.
// ============================================================================

#define NT    512
#define GRID  148
#define AP    272
#define WIMG  84096
#define WARP_ABUF (32 * AP)
#define SMEM_BYTES (WIMG + 16 * WARP_ABUF)

// stage bases (bytes). LSTM layer: [IG groups][O frags]; sizes as before.
#define WB_L0 0
#define WB_L1 24576
#define WB_L2 36864
#define WB_L3 49152
#define WB_L4 61440
#define WB_FC 73728
#define BIAS_OFF 81920

#define LOG2E  1.4426950408889634f
#define LOG2E2 2.8853901617765427f

__device__ __align__(16) unsigned char g_img[WIMG];

// ---------------- scalar fast math ----------------
__device__ __forceinline__ float ex2f(float x) {
    float y; asm("ex2.approx.f32 %0, %1;" : "=f"(y) : "f"(x)); return y;
}
__device__ __forceinline__ float rcpf(float x) {
    float y; asm("rcp.approx.f32 %0, %1;" : "=f"(y) : "f"(x)); return y;
}
__device__ __forceinline__ uint32_t packbf2(float a, float b) {
    float2 t = make_float2(a, b);
    __nv_bfloat162 v = __float22bfloat162_rn(t);
    return *reinterpret_cast<uint32_t*>(&v);
}
__device__ __forceinline__ float bflo(float v) {
    return v - __bfloat162float(__float2bfloat16_rn(v));
}

// ---------------- packed f32x2 helpers ----------------
__device__ __forceinline__ uint64_t pk2(float a, float b) {
    uint64_t r; asm("mov.b64 %0, {%1, %2};" : "=l"(r) : "f"(a), "f"(b)); return r;
}
__device__ __forceinline__ void upk2(uint64_t v, float& a, float& b) {
    asm("mov.b64 {%0, %1}, %2;" : "=f"(a), "=f"(b) : "l"(v));
}
__device__ __forceinline__ uint64_t fma2(uint64_t a, uint64_t b, uint64_t c) {
    uint64_t d;
    asm("fma.rn.f32x2 %0, %1, %2, %3;" : "=l"(d) : "l"(a), "l"(b), "l"(c));
    return d;
}

// ---------------- mma ----------------
__device__ __forceinline__ void mma_bf16(float c[4],
    const uint32_t a[4], uint32_t b0, uint32_t b1) {
    asm volatile(
        "mma.sync.aligned.m16n8k16.row.col.f32.bf16.bf16.f32 "
        "{%0,%1,%2,%3},{%4,%5,%6,%7},{%8,%9},{%0,%1,%2,%3};"
        : "+f"(c[0]), "+f"(c[1]), "+f"(c[2]), "+f"(c[3])
        : "r"(a[0]), "r"(a[1]), "r"(a[2]), "r"(a[3]), "r"(b0), "r"(b1));
}

// ---------------- weight pack: layout v2 ----------------
// LSTM stage s (KH = 4 for L0 else 2): 2KH kidx x 4 ntj.
//   IG group (kidx,ntj) at base + (kidx*4+ntj)*512: per lane 16B = i0,i1,g0,g1
//   O frag at base + KH*4096 + (kidx*4+ntj)*256: per lane 8B = o0,o1
// FC: 4 kidx x 8 ntj paired: base + (kidx*4 + ntj/2)*512 + lane*16 + (ntj&1)*8
// Biases pre-scaled (i,o rows by log2e; g rows by 2*log2e).
__global__ void _LSTM_pack(const float* __restrict__ w_ih0,
                           const float* __restrict__ w_ih_rest,
                           const float* __restrict__ b_ih,
                           const float* __restrict__ b_hh,
                           const float* __restrict__ fc_w,
                           const float* __restrict__ fc_b) {
    int i = blockIdx.x * blockDim.x + threadIdx.x;
    if (i < 40960) {
        int s, q;
        if (i < 12288)       { s = 0; q = i; }
        else if (i < 36864)  { s = 1 + (i - 12288) / 6144; q = (i - 12288) % 6144; }
        else                 { s = 5; q = i - 36864; }
        int fid = q >> 7, r = q & 127;
        int lane = r >> 2, reg = (r >> 1) & 1, half = r & 1;
        int n = lane >> 2;
        int kel = (lane & 3) * 2 + half + reg * 8;
        float w; unsigned dst;
        if (s < 5) {
            const int KH = (s == 0) ? 4 : 2;
            const unsigned base =
                (s == 0) ? 0u : (unsigned)(24576 + (s - 1) * 12288);
            int kidx = fid / 12, nt = fid % 12;
            int gate = nt >> 2, ntj = nt & 3;
            int is_lo = kidx >= KH;
            int k = (is_lo ? kidx - KH : kidx) * 16 + kel;
            int j = gate * 32 + ntj * 8 + n;
            int rr = (j < 32) ? j : j + 32;
            if (s == 0) w = w_ih0[rr * 64 + k];
            else        w = w_ih_rest[(s - 1) * 4096 + rr * 32 + k];
            __nv_bfloat16 hi = __float2bfloat16_rn(w);
            __nv_bfloat16 v = is_lo ?
                __float2bfloat16_rn(w - __bfloat162float(hi)) : hi;
            if (gate < 2)
                dst = base + (unsigned)(kidx * 4 + ntj) * 512
                    + lane * 16 + gate * 8 + reg * 4 + half * 2;
            else
                dst = base + (unsigned)KH * 4096 + (unsigned)(kidx * 4 + ntj) * 256
                    + lane * 8 + reg * 4 + half * 2;
            *(__nv_bfloat16*)(g_img + dst) = v;
        } else {
            int kidx = fid / 8, nt = fid % 8;   // fid 0..31
            int is_lo = kidx >= 2;
            int k = (is_lo ? kidx - 2 : kidx) * 16 + kel;
            int j = nt * 8 + n;
            w = fc_w[j * 32 + k];
            __nv_bfloat16 hi = __float2bfloat16_rn(w);
            __nv_bfloat16 v = is_lo ?
                __float2bfloat16_rn(w - __bfloat162float(hi)) : hi;
            dst = WB_FC + (unsigned)(kidx * 4 + (nt >> 1)) * 512
                + lane * 16 + (nt & 1) * 8 + reg * 4 + half * 2;
            *(__nv_bfloat16*)(g_img + dst) = v;
        }
    } else if (i < 40960 + 544) {
        int b = i - 40960; float v;
        if (b < 480) {
            int l = b / 96, j = b % 96;
            int rr = (j < 32) ? j : j + 32;
            v = b_ih[l * 128 + rr] + b_hh[l * 128 + rr];
            v *= (j >= 32 && j < 64) ? LOG2E2 : LOG2E;
        } else v = fc_b[b - 480];
        *(float*)(g_img + BIAS_OFF + b * 4) = v;
    }
}

// packed activation for a pair of h: inputs are packed accum pairs + packed
// pre-scaled bias pairs. Returns packed f32x2 h pair.
__device__ __forceinline__ uint64_t act_h2(
    uint64_t ci2, uint64_t cg2, uint64_t co2,
    uint64_t bi2, uint64_t bg2, uint64_t bo2,
    uint64_t cL1, uint64_t cL2, uint64_t ONE2, uint64_t MONE2, uint64_t ZERO2)
{
    uint64_t ui = fma2(ci2, cL1, bi2);
    uint64_t ug = fma2(cg2, cL2, bg2);
    uint64_t uo = fma2(co2, cL1, bo2);
    float u0, u1;
    upk2(ui, u0, u1); uint64_t A  = pk2(ex2f(u0), ex2f(u1));
    upk2(ug, u0, u1); uint64_t Bv = pk2(ex2f(u0), ex2f(u1));
    upk2(uo, u0, u1); uint64_t Cc = pk2(ex2f(u0), ex2f(u1));
    uint64_t Ap1 = fma2(A,  ONE2, ONE2);
    uint64_t Bp1 = fma2(Bv, ONE2, ONE2);
    uint64_t Bm1 = fma2(Bv, ONE2, MONE2);
    uint64_t den = fma2(Ap1, Bp1, ZERO2);
    upk2(den, u0, u1); uint64_t rr1 = pk2(rcpf(u0), rcpf(u1));
    uint64_t num = fma2(A, Bm1, ZERO2);
    uint64_t c2k = fma2(fma2(num, rr1, ZERO2), cL2, ZERO2);
    upk2(c2k, u0, u1); uint64_t D = pk2(ex2f(u0), ex2f(u1));
    uint64_t Cp1 = fma2(Cc, ONE2, ONE2);
    uint64_t Dp1 = fma2(D,  ONE2, ONE2);
    uint64_t Dm1 = fma2(D,  ONE2, MONE2);
    uint64_t dn2 = fma2(Cp1, Dp1, ZERO2);
    upk2(dn2, u0, u1); uint64_t rr2 = pk2(rcpf(u0), rcpf(u1));
    return fma2(fma2(Cc, Dm1, ZERO2), rr2, ZERO2);
}

// write a packed h pair (hi bf16x2 + lo bf16x2) to smem
__device__ __forceinline__ void store_h2(uint64_t h2, unsigned char* r0) {
    float h0, h1; upk2(h2, h0, h1);
    uint32_t hip = packbf2(h0, h1);
    uint32_t bl = hip << 16, bh = hip & 0xFFFF0000u;
    float l0 = h0 - __uint_as_float(bl);
    float l1 = h1 - __uint_as_float(bh);
    *(uint32_t*)r0        = hip;
    *(uint32_t*)(r0 + 64) = packbf2(l0, l1);
}

// -------- one 96-col LSTM layer (R8 streaming structure, v2 loads) --------
template<int KH>
__device__ __forceinline__ void layer96(
    const unsigned char* __restrict__ wimg, uint32_t wbase,
    const float* __restrict__ biasK, unsigned char* __restrict__ Abuf,
    int in_hi, int in_lo, int out_off, int lane,
    uint64_t cL1, uint64_t cL2, uint64_t ONE2, uint64_t MONE2, uint64_t ZERO2)
{
    const int g = lane >> 2, q4 = lane & 3;
    uint32_t Ah[2][KH][4];
#pragma unroll
    for (int m = 0; m < 2; m++)
#pragma unroll
        for (int tk = 0; tk < KH; tk++) {
            const unsigned char* ab =
                Abuf + in_hi + (m * 16 + g) * AP + 32 * tk + 4 * q4;
            Ah[m][tk][0] = *(const uint32_t*)ab;
            Ah[m][tk][1] = *(const uint32_t*)(ab + 8 * AP);
            Ah[m][tk][2] = *(const uint32_t*)(ab + 16);
            Ah[m][tk][3] = *(const uint32_t*)(ab + 8 * AP + 16);
        }
    __syncwarp();

    const unsigned char* wIG = wimg + wbase + lane * 16;
    const unsigned char* wO  = wimg + wbase + KH * 4096 + lane * 8;
    const unsigned char* lo0 = Abuf + in_lo + g * AP + 4 * q4;
    const unsigned char* lo1 = lo0 + 16 * AP;

#pragma unroll
    for (int ntj = 0; ntj < 4; ntj++) {
        const unsigned char* aIG = wIG + ntj * 512;
        const unsigned char* aO  = wO  + ntj * 256;
        float Ci[2][4], Cg[2][4], Co[2][4];
#pragma unroll
        for (int m = 0; m < 2; m++)
#pragma unroll
            for (int q = 0; q < 4; q++) {
                Ci[m][q] = 0.f; Cg[m][q] = 0.f; Co[m][q] = 0.f;
            }
#pragma unroll
        for (int t = 0; t < 3 * KH; t++) {
            const int seg = t / KH, tk = t % KH;
            const int kidx = (seg == 1) ? KH + tk : tk;
            uint4 igf = *(const uint4*)(aIG + kidx * 2048);
            uint2 of  = *(const uint2*)(aO  + kidx * 1024);
#pragma unroll
            for (int m = 0; m < 2; m++) {
                uint32_t Ax[4];
                if (seg == 2) {
                    const unsigned char* ab = (m ? lo1 : lo0) + 32 * tk;
                    Ax[0] = *(const uint32_t*)ab;
                    Ax[1] = *(const uint32_t*)(ab + 8 * AP);
                    Ax[2] = *(const uint32_t*)(ab + 16);
                    Ax[3] = *(const uint32_t*)(ab + 8 * AP + 16);
                } else {
                    Ax[0] = Ah[m][tk][0]; Ax[1] = Ah[m][tk][1];
                    Ax[2] = Ah[m][tk][2]; Ax[3] = Ah[m][tk][3];
                }
                mma_bf16(Ci[m], Ax, igf.x, igf.y);
                mma_bf16(Cg[m], Ax, igf.z, igf.w);
                mma_bf16(Co[m], Ax, of.x,  of.y);
            }
        }
        const int col = ntj * 8 + q4 * 2;
        uint64_t bi2 = *(const uint64_t*)(biasK + col);
        uint64_t bg2 = *(const uint64_t*)(biasK + 32 + col);
        uint64_t bo2 = *(const uint64_t*)(biasK + 64 + col);
#pragma unroll
        for (int m = 0; m < 2; m++) {
            unsigned char* r0 =
                Abuf + out_off + (m * 16 + g) * AP + 4 * (ntj * 4 + q4);
            uint64_t hA = act_h2(pk2(Ci[m][0], Ci[m][1]),
                                 pk2(Cg[m][0], Cg[m][1]),
                                 pk2(Co[m][0], Co[m][1]),
                                 bi2, bg2, bo2, cL1, cL2, ONE2, MONE2, ZERO2);
            store_h2(hA, r0);
            uint64_t hB = act_h2(pk2(Ci[m][2], Ci[m][3]),
                                 pk2(Cg[m][2], Cg[m][3]),
                                 pk2(Co[m][2], Co[m][3]),
                                 bi2, bg2, bo2, cL1, cL2, ONE2, MONE2, ZERO2);
            store_h2(hB, r0 + 8 * AP);
        }
    }
    __syncwarp();
}

// -------- fc: A hi+lo in regs; paired-ntj LDS.128 weights --------
__device__ __forceinline__ void fc_stage(
    const unsigned char* __restrict__ wimg,
    const float* __restrict__ fb, unsigned char* __restrict__ Abuf, int lane,
    uint64_t ONE2, uint64_t ZERO2)
{
    const int g = lane >> 2, q4 = lane & 3;
    uint32_t Ah[2][2][4], Al[2][2][4];
#pragma unroll
    for (int m = 0; m < 2; m++)
#pragma unroll
        for (int tk = 0; tk < 2; tk++) {
            const unsigned char* ab =
                Abuf + (m * 16 + g) * AP + 32 * tk + 4 * q4;
            Ah[m][tk][0] = *(const uint32_t*)ab;
            Ah[m][tk][1] = *(const uint32_t*)(ab + 8 * AP);
            Ah[m][tk][2] = *(const uint32_t*)(ab + 16);
            Ah[m][tk][3] = *(const uint32_t*)(ab + 8 * AP + 16);
            const unsigned char* al = ab + 64;
            Al[m][tk][0] = *(const uint32_t*)al;
            Al[m][tk][1] = *(const uint32_t*)(al + 8 * AP);
            Al[m][tk][2] = *(const uint32_t*)(al + 16);
            Al[m][tk][3] = *(const uint32_t*)(al + 8 * AP + 16);
        }
    __syncwarp();

    const unsigned char* wp = wimg + WB_FC + lane * 16;

#pragma unroll
    for (int np = 0; np < 4; np++) {           // ntj pairs (2n0, 2n0+1)
        float C0[2][4], C1[2][4];
#pragma unroll
        for (int m = 0; m < 2; m++)
#pragma unroll
            for (int q = 0; q < 4; q++) { C0[m][q] = 0.f; C1[m][q] = 0.f; }
#pragma unroll
        for (int t = 0; t < 6; t++) {
            const int seg = t / 2, tk = t % 2;
            const int kidx = (seg == 1) ? 2 + tk : tk;
            uint4 bf = *(const uint4*)(wp + (uint32_t)(kidx * 4 + np) * 512);
#pragma unroll
            for (int m = 0; m < 2; m++) {
                const uint32_t* A = (seg == 2) ? Al[m][tk] : Ah[m][tk];
                mma_bf16(C0[m], A, bf.x, bf.y);
                mma_bf16(C1[m], A, bf.z, bf.w);
            }
        }
#pragma unroll
        for (int half = 0; half < 2; half++) {
            float (*C)[4] = half ? C1 : C0;
            const int col = (np * 2 + half) * 8 + q4 * 2;
            uint64_t fb2 = *(const uint64_t*)(fb + col);
#pragma unroll
            for (int m = 0; m < 2; m++) {
                unsigned char* r0 = Abuf + (m * 16 + g) * AP + 4 * col;
                *(uint64_t*)r0 = fma2(pk2(C[m][0], C[m][1]), ONE2, fb2);
                *(uint64_t*)(r0 + 8 * AP) = fma2(pk2(C[m][2], C[m][3]), ONE2, fb2);
            }
        }
    }
    __syncwarp();
}

// ---------------- main persistent kernel ----------------
__global__ void __launch_bounds__(NT, 1)
_LSTM_main(const float* __restrict__ x, float* __restrict__ out, int B) {
    extern __shared__ unsigned char smem[];
    const int tid = threadIdx.x;
    const int wid = tid >> 5;
    const int lane = tid & 31;

#pragma unroll 4
    for (int p = tid; p < WIMG / 16; p += NT)
        ((uint4*)smem)[p] = ((const uint4*)g_img)[p];
    __syncthreads();

    unsigned char* Abuf = smem + WIMG + wid * WARP_ABUF;
    const float* biasK = (const float*)(smem + BIAS_OFF);
    const float4* x4 = (const float4*)x;
    float4* o4 = (float4*)out;

    const uint64_t cL1  = pk2(LOG2E, LOG2E);
    const uint64_t cL2  = pk2(LOG2E2, LOG2E2);
    const uint64_t ONE2 = pk2(1.0f, 1.0f);
    const uint64_t MONE2 = pk2(-1.0f, -1.0f);
    const uint64_t ZERO2 = pk2(0.0f, 0.0f);

    const int npair = (B + 511) >> 9;

#pragma unroll 1
    for (int it = blockIdx.x; it < npair; it += GRID) {
        const long long rowbase = (long long)it * 512 + wid * 32;

        // ---- load 32 x-rows, bf16 hi [0,128) / lo [128,256) ----
#pragma unroll
        for (int i = 0; i < 16; i++) {
            int p = lane + i * 32;
            int r = p >> 4, c4 = p & 15;
            long long grow = rowbase + r;
            float4 v = (grow < B) ? x4[grow * 16 + c4]
                                  : make_float4(0.f, 0.f, 0.f, 0.f);
            uint32_t hi0 = packbf2(v.x, v.y), hi1 = packbf2(v.z, v.w);
            uint32_t lo0 = packbf2(bflo(v.x), bflo(v.y));
            uint32_t lo1 = packbf2(bflo(v.z), bflo(v.w));
            unsigned char* dst = Abuf + r * AP + 8 * c4;
            *(uint2*)dst         = make_uint2(hi0, hi1);
            *(uint2*)(dst + 128) = make_uint2(lo0, lo1);
        }
        __syncwarp();

        // ---- 5 LSTM layers (ping-pong h regions) + fc ----
        layer96<4>(smem, WB_L0, biasK,       Abuf,   0, 128,   0, lane,
                   cL1, cL2, ONE2, MONE2, ZERO2);
        layer96<2>(smem, WB_L1, biasK + 96,  Abuf,   0,  64, 128, lane,
                   cL1, cL2, ONE2, MONE2, ZERO2);
        layer96<2>(smem, WB_L2, biasK + 192, Abuf, 128, 192,   0, lane,
                   cL1, cL2, ONE2, MONE2, ZERO2);
        layer96<2>(smem, WB_L3, biasK + 288, Abuf,   0,  64, 128, lane,
                   cL1, cL2, ONE2, MONE2, ZERO2);
        layer96<2>(smem, WB_L4, biasK + 384, Abuf, 128, 192,   0, lane,
                   cL1, cL2, ONE2, MONE2, ZERO2);
        fc_stage(smem, biasK + 480, Abuf, lane, ONE2, ZERO2);

        // ---- coalesced f32 store ----
#pragma unroll
        for (int i = 0; i < 16; i++) {
            int p = lane + i * 32;
            int r = p >> 4, c4 = p & 15;
            long long grow = rowbase + r;
            if (grow < B)
                o4[grow * 16 + c4] = *(const float4*)(Abuf + r * AP + 16 * c4);
        }
        __syncwarp();
    }
}

// ---------------- launch ----------------
extern "C" void kernel_launch(void* const* d_in, const int* in_sizes, int n_in,
                              void* d_out, int out_size) {
    (void)n_in; (void)out_size;
    const float* x         = (const float*)d_in[0];
    const float* w_ih0     = (const float*)d_in[1];
    // d_in[2] = w_hh0      (unused: h0 == 0, T == 1)
    const float* w_ih_rest = (const float*)d_in[3];
    // d_in[4] = w_hh_rest  (unused)
    const float* b_ih      = (const float*)d_in[5];
    const float* b_hh      = (const float*)d_in[6];
    const float* fc_w      = (const float*)d_in[7];
    const float* fc_b      = (const float*)d_in[8];
    float* out = (float*)d_out;

    int B = in_sizes[0] / 64;

    _LSTM_pack<<<(40960 + 544 + 255) / 256, 256>>>(
        w_ih0, w_ih_rest, b_ih, b_hh, fc_w, fc_b);

    cudaFuncSetAttribute(_LSTM_main,
                         cudaFuncAttributeMaxDynamicSharedMemorySize, SMEM_BYTES);
    int npair = (B + 511) / 512;
    int grid = npair < GRID ? npair : GRID;
    _LSTM_main<<<grid, NT, SMEM_BYTES>>>(x, out, B);
}

// round 10
// speedup vs baseline: 1.1865x; 1.1865x over previous
#include <cuda_runtime.h>
#include <cuda_fp16.h>
#include <cstdint>

// ============================================================================
// T=1, h0=c0=0 => w_hh* unused, f-gate unused. Chain of small GEMMs on HMMA
// (mma.sync m16n8k16 fp16 -> f32 accum).
// R10 precision scheme (fp16x2, 2 passes instead of bf16x3's 3):
//   W = W_hi + W_lo (both fp16; exact to 2^-22), A = fp16(x) single.
//   gates = A*W_hi + A*W_lo = A*W exactly; only A-quantization (2^-11)
//   is dropped -> predicted final rel_err ~3e-5 (<< 1e-3).
// Consequences: 1/3 fewer MMAs, no A_lo storage/loads/conversions, h stored
// as a single fp16x2 word, A fully in registers for every layer.
// Persistent: 148 CTAs x 512 thr; warp owns 32 rows, warp-private A smem.
// ============================================================================

#define NT    512
#define GRID  148
#define AP    272
#define WIMG  84096
#define WARP_ABUF (32 * AP)
#define SMEM_BYTES (WIMG + 16 * WARP_ABUF)

// stage bases (bytes); per LSTM stage: [IG groups][O frags], hi then lo kidx
#define WB_L0 0
#define WB_L1 24576
#define WB_L2 36864
#define WB_L3 49152
#define WB_L4 61440
#define WB_FC 73728
#define BIAS_OFF 81920

#define LOG2E  1.4426950408889634f
#define LOG2E2 2.8853901617765427f

__device__ __align__(16) unsigned char g_img[WIMG];

// ---------------- scalar fast math ----------------
__device__ __forceinline__ float ex2f(float x) {
    float y; asm("ex2.approx.f32 %0, %1;" : "=f"(y) : "f"(x)); return y;
}
__device__ __forceinline__ float rcpf(float x) {
    float y; asm("rcp.approx.f32 %0, %1;" : "=f"(y) : "f"(x)); return y;
}

// ---------------- packed f32x2 helpers ----------------
__device__ __forceinline__ uint64_t pk2(float a, float b) {
    uint64_t r; asm("mov.b64 %0, {%1, %2};" : "=l"(r) : "f"(a), "f"(b)); return r;
}
__device__ __forceinline__ void upk2(uint64_t v, float& a, float& b) {
    asm("mov.b64 {%0, %1}, %2;" : "=f"(a), "=f"(b) : "l"(v));
}
__device__ __forceinline__ uint64_t fma2(uint64_t a, uint64_t b, uint64_t c) {
    uint64_t d;
    asm("fma.rn.f32x2 %0, %1, %2, %3;" : "=l"(d) : "l"(a), "l"(b), "l"(c));
    return d;
}
__device__ __forceinline__ uint32_t packh2(float a, float b) {
    __half2 v = __float22half2_rn(make_float2(a, b));
    return *reinterpret_cast<uint32_t*>(&v);
}

// ---------------- mma (fp16 inputs, f32 accum) ----------------
__device__ __forceinline__ void mma_f16(float c[4],
    const uint32_t a[4], uint32_t b0, uint32_t b1) {
    asm volatile(
        "mma.sync.aligned.m16n8k16.row.col.f32.f16.f16.f32 "
        "{%0,%1,%2,%3},{%4,%5,%6,%7},{%8,%9},{%0,%1,%2,%3};"
        : "+f"(c[0]), "+f"(c[1]), "+f"(c[2]), "+f"(c[3])
        : "r"(a[0]), "r"(a[1]), "r"(a[2]), "r"(a[3]), "r"(b0), "r"(b1));
}

// ---------------- weight pack: v2 layout, fp16 hi/lo ----------------
// LSTM stage s (KH = 4 for L0 else 2): kidx 0..2KH-1 (hi then lo) x 4 ntj.
//   IG group (kidx,ntj) at base + (kidx*4+ntj)*512: per lane 16B = i0,i1,g0,g1
//   O frag at base + KH*4096 + (kidx*4+ntj)*256: per lane 8B = o0,o1
// FC: kidx 0..3 (2 hi, 2 lo) x 8 ntj paired:
//   base + (kidx*4 + ntj/2)*512 + lane*16 + (ntj&1)*8
// Biases pre-scaled (i,o rows by log2e; g rows by 2*log2e).
__global__ void _LSTM_pack(const float* __restrict__ w_ih0,
                           const float* __restrict__ w_ih_rest,
                           const float* __restrict__ b_ih,
                           const float* __restrict__ b_hh,
                           const float* __restrict__ fc_w,
                           const float* __restrict__ fc_b) {
    int i = blockIdx.x * blockDim.x + threadIdx.x;
    if (i < 40960) {
        int s, q;
        if (i < 12288)       { s = 0; q = i; }
        else if (i < 36864)  { s = 1 + (i - 12288) / 6144; q = (i - 12288) % 6144; }
        else                 { s = 5; q = i - 36864; }
        int fid = q >> 7, r = q & 127;
        int lane = r >> 2, reg = (r >> 1) & 1, half = r & 1;
        int n = lane >> 2;
        int kel = (lane & 3) * 2 + half + reg * 8;
        float w; unsigned dst;
        if (s < 5) {
            const int KH = (s == 0) ? 4 : 2;
            const unsigned base =
                (s == 0) ? 0u : (unsigned)(24576 + (s - 1) * 12288);
            int kidx = fid / 12, nt = fid % 12;
            int gate = nt >> 2, ntj = nt & 3;
            int is_lo = kidx >= KH;
            int k = (is_lo ? kidx - KH : kidx) * 16 + kel;
            int j = gate * 32 + ntj * 8 + n;
            int rr = (j < 32) ? j : j + 32;
            if (s == 0) w = w_ih0[rr * 64 + k];
            else        w = w_ih_rest[(s - 1) * 4096 + rr * 32 + k];
            __half hi = __float2half_rn(w);
            __half v = is_lo ? __float2half_rn(w - __half2float(hi)) : hi;
            if (gate < 2)
                dst = base + (unsigned)(kidx * 4 + ntj) * 512
                    + lane * 16 + gate * 8 + reg * 4 + half * 2;
            else
                dst = base + (unsigned)KH * 4096 + (unsigned)(kidx * 4 + ntj) * 256
                    + lane * 8 + reg * 4 + half * 2;
            *(__half*)(g_img + dst) = v;
        } else {
            int kidx = fid / 8, nt = fid % 8;   // fid 0..31
            int is_lo = kidx >= 2;
            int k = (is_lo ? kidx - 2 : kidx) * 16 + kel;
            int j = nt * 8 + n;
            w = fc_w[j * 32 + k];
            __half hi = __float2half_rn(w);
            __half v = is_lo ? __float2half_rn(w - __half2float(hi)) : hi;
            dst = WB_FC + (unsigned)(kidx * 4 + (nt >> 1)) * 512
                + lane * 16 + (nt & 1) * 8 + reg * 4 + half * 2;
            *(__half*)(g_img + dst) = v;
        }
    } else if (i < 40960 + 544) {
        int b = i - 40960; float v;
        if (b < 480) {
            int l = b / 96, j = b % 96;
            int rr = (j < 32) ? j : j + 32;
            v = b_ih[l * 128 + rr] + b_hh[l * 128 + rr];
            v *= (j >= 32 && j < 64) ? LOG2E2 : LOG2E;
        } else v = fc_b[b - 480];
        *(float*)(g_img + BIAS_OFF + b * 4) = v;
    }
}

// packed fused activation: h pair from packed accum + pre-scaled bias pairs.
__device__ __forceinline__ uint64_t act_h2(
    uint64_t ci2, uint64_t cg2, uint64_t co2,
    uint64_t bi2, uint64_t bg2, uint64_t bo2,
    uint64_t cL1, uint64_t cL2, uint64_t ONE2, uint64_t MONE2, uint64_t ZERO2)
{
    uint64_t ui = fma2(ci2, cL1, bi2);
    uint64_t ug = fma2(cg2, cL2, bg2);
    uint64_t uo = fma2(co2, cL1, bo2);
    float u0, u1;
    upk2(ui, u0, u1); uint64_t A  = pk2(ex2f(u0), ex2f(u1));
    upk2(ug, u0, u1); uint64_t Bv = pk2(ex2f(u0), ex2f(u1));
    upk2(uo, u0, u1); uint64_t Cc = pk2(ex2f(u0), ex2f(u1));
    uint64_t Ap1 = fma2(A,  ONE2, ONE2);
    uint64_t Bp1 = fma2(Bv, ONE2, ONE2);
    uint64_t Bm1 = fma2(Bv, ONE2, MONE2);
    uint64_t den = fma2(Ap1, Bp1, ZERO2);
    upk2(den, u0, u1); uint64_t rr1 = pk2(rcpf(u0), rcpf(u1));
    uint64_t num = fma2(A, Bm1, ZERO2);
    uint64_t c2k = fma2(fma2(num, rr1, ZERO2), cL2, ZERO2);
    upk2(c2k, u0, u1); uint64_t D = pk2(ex2f(u0), ex2f(u1));
    uint64_t Cp1 = fma2(Cc, ONE2, ONE2);
    uint64_t Dp1 = fma2(D,  ONE2, ONE2);
    uint64_t Dm1 = fma2(D,  ONE2, MONE2);
    uint64_t dn2 = fma2(Cp1, Dp1, ZERO2);
    upk2(dn2, u0, u1); uint64_t rr2 = pk2(rcpf(u0), rcpf(u1));
    return fma2(fma2(Cc, Dm1, ZERO2), rr2, ZERO2);
}

// -------- one 96-col LSTM layer: A fully in regs, in-place h --------
template<int KH>
__device__ __forceinline__ void layer96(
    const unsigned char* __restrict__ wimg, uint32_t wbase,
    const float* __restrict__ biasK, unsigned char* __restrict__ Abuf,
    int lane,
    uint64_t cL1, uint64_t cL2, uint64_t ONE2, uint64_t MONE2, uint64_t ZERO2)
{
    const int g = lane >> 2, q4 = lane & 3;
    uint32_t Ah[2][KH][4];
#pragma unroll
    for (int m = 0; m < 2; m++)
#pragma unroll
        for (int tk = 0; tk < KH; tk++) {
            const unsigned char* ab =
                Abuf + (m * 16 + g) * AP + 32 * tk + 4 * q4;
            Ah[m][tk][0] = *(const uint32_t*)ab;
            Ah[m][tk][1] = *(const uint32_t*)(ab + 8 * AP);
            Ah[m][tk][2] = *(const uint32_t*)(ab + 16);
            Ah[m][tk][3] = *(const uint32_t*)(ab + 8 * AP + 16);
        }
    __syncwarp();   // all lanes' A in regs before any h writes below

    const unsigned char* wIG = wimg + wbase + lane * 16;
    const unsigned char* wO  = wimg + wbase + KH * 4096 + lane * 8;

#pragma unroll
    for (int ntj = 0; ntj < 4; ntj++) {
        const unsigned char* aIG = wIG + ntj * 512;
        const unsigned char* aO  = wO  + ntj * 256;
        float Ci[2][4], Cg[2][4], Co[2][4];
#pragma unroll
        for (int m = 0; m < 2; m++)
#pragma unroll
            for (int q = 0; q < 4; q++) {
                Ci[m][q] = 0.f; Cg[m][q] = 0.f; Co[m][q] = 0.f;
            }
#pragma unroll
        for (int t = 0; t < 2 * KH; t++) {       // kidx = t (W hi then W lo)
            const int tk = t & (KH - 1);         // A reused for both segments
            uint4 igf = *(const uint4*)(aIG + t * 2048);
            uint2 of  = *(const uint2*)(aO  + t * 1024);
#pragma unroll
            for (int m = 0; m < 2; m++) {
                mma_f16(Ci[m], Ah[m][tk], igf.x, igf.y);
                mma_f16(Cg[m], Ah[m][tk], igf.z, igf.w);
                mma_f16(Co[m], Ah[m][tk], of.x,  of.y);
            }
        }
        const int col = ntj * 8 + q4 * 2;
        uint64_t bi2 = *(const uint64_t*)(biasK + col);
        uint64_t bg2 = *(const uint64_t*)(biasK + 32 + col);
        uint64_t bo2 = *(const uint64_t*)(biasK + 64 + col);
#pragma unroll
        for (int m = 0; m < 2; m++) {
            unsigned char* r0 =
                Abuf + (m * 16 + g) * AP + 4 * (ntj * 4 + q4);
            uint64_t hA = act_h2(pk2(Ci[m][0], Ci[m][1]),
                                 pk2(Cg[m][0], Cg[m][1]),
                                 pk2(Co[m][0], Co[m][1]),
                                 bi2, bg2, bo2, cL1, cL2, ONE2, MONE2, ZERO2);
            uint64_t hB = act_h2(pk2(Ci[m][2], Ci[m][3]),
                                 pk2(Cg[m][2], Cg[m][3]),
                                 pk2(Co[m][2], Co[m][3]),
                                 bi2, bg2, bo2, cL1, cL2, ONE2, MONE2, ZERO2);
            float h0, h1;
            upk2(hA, h0, h1);
            *(uint32_t*)r0 = packh2(h0, h1);
            upk2(hB, h0, h1);
            *(uint32_t*)(r0 + 8 * AP) = packh2(h0, h1);
        }
    }
    __syncwarp();
}

// -------- fc: A in regs; paired-ntj LDS.128 weights; f32 out staged --------
__device__ __forceinline__ void fc_stage(
    const unsigned char* __restrict__ wimg,
    const float* __restrict__ fb, unsigned char* __restrict__ Abuf, int lane,
    uint64_t ONE2)
{
    const int g = lane >> 2, q4 = lane & 3;
    uint32_t Ah[2][2][4];
#pragma unroll
    for (int m = 0; m < 2; m++)
#pragma unroll
        for (int tk = 0; tk < 2; tk++) {
            const unsigned char* ab =
                Abuf + (m * 16 + g) * AP + 32 * tk + 4 * q4;
            Ah[m][tk][0] = *(const uint32_t*)ab;
            Ah[m][tk][1] = *(const uint32_t*)(ab + 8 * AP);
            Ah[m][tk][2] = *(const uint32_t*)(ab + 16);
            Ah[m][tk][3] = *(const uint32_t*)(ab + 8 * AP + 16);
        }
    __syncwarp();

    const unsigned char* wp = wimg + WB_FC + lane * 16;

#pragma unroll
    for (int np = 0; np < 4; np++) {           // ntj pairs (2np, 2np+1)
        float C0[2][4], C1[2][4];
#pragma unroll
        for (int m = 0; m < 2; m++)
#pragma unroll
            for (int q = 0; q < 4; q++) { C0[m][q] = 0.f; C1[m][q] = 0.f; }
#pragma unroll
        for (int t = 0; t < 4; t++) {          // kidx = t (2 hi, 2 lo)
            const int tk = t & 1;
            uint4 bf = *(const uint4*)(wp + (uint32_t)(t * 4 + np) * 512);
#pragma unroll
            for (int m = 0; m < 2; m++) {
                mma_f16(C0[m], Ah[m][tk], bf.x, bf.y);
                mma_f16(C1[m], Ah[m][tk], bf.z, bf.w);
            }
        }
#pragma unroll
        for (int half = 0; half < 2; half++) {
            float (*C)[4] = half ? C1 : C0;
            const int col = (np * 2 + half) * 8 + q4 * 2;
            uint64_t fb2 = *(const uint64_t*)(fb + col);
#pragma unroll
            for (int m = 0; m < 2; m++) {
                unsigned char* r0 = Abuf + (m * 16 + g) * AP + 4 * col;
                *(uint64_t*)r0 = fma2(pk2(C[m][0], C[m][1]), ONE2, fb2);
                *(uint64_t*)(r0 + 8 * AP) = fma2(pk2(C[m][2], C[m][3]), ONE2, fb2);
            }
        }
    }
    __syncwarp();
}

// ---------------- main persistent kernel ----------------
__global__ void __launch_bounds__(NT, 1)
_LSTM_main(const float* __restrict__ x, float* __restrict__ out, int B) {
    extern __shared__ unsigned char smem[];
    const int tid = threadIdx.x;
    const int wid = tid >> 5;
    const int lane = tid & 31;

#pragma unroll 4
    for (int p = tid; p < WIMG / 16; p += NT)
        ((uint4*)smem)[p] = ((const uint4*)g_img)[p];
    __syncthreads();

    unsigned char* Abuf = smem + WIMG + wid * WARP_ABUF;
    const float* biasK = (const float*)(smem + BIAS_OFF);
    const float4* x4 = (const float4*)x;
    float4* o4 = (float4*)out;

    const uint64_t cL1   = pk2(LOG2E, LOG2E);
    const uint64_t cL2   = pk2(LOG2E2, LOG2E2);
    const uint64_t ONE2  = pk2(1.0f, 1.0f);
    const uint64_t MONE2 = pk2(-1.0f, -1.0f);
    const uint64_t ZERO2 = pk2(0.0f, 0.0f);

    const int npair = (B + 511) >> 9;

#pragma unroll 1
    for (int it = blockIdx.x; it < npair; it += GRID) {
        const long long rowbase = (long long)it * 512 + wid * 32;

        // ---- load 32 x-rows, convert to fp16, stage (row = 128B) ----
#pragma unroll
        for (int i = 0; i < 16; i++) {
            int p = lane + i * 32;
            int r = p >> 4, c4 = p & 15;
            long long grow = rowbase + r;
            float4 v = (grow < B) ? x4[grow * 16 + c4]
                                  : make_float4(0.f, 0.f, 0.f, 0.f);
            uint32_t h0 = packh2(v.x, v.y), h1 = packh2(v.z, v.w);
            *(uint2*)(Abuf + r * AP + 8 * c4) = make_uint2(h0, h1);
        }
        __syncwarp();

        // ---- 5 LSTM layers (in-place, A in regs) + fc ----
        layer96<4>(smem, WB_L0, biasK,       Abuf, lane, cL1, cL2, ONE2, MONE2, ZERO2);
        layer96<2>(smem, WB_L1, biasK + 96,  Abuf, lane, cL1, cL2, ONE2, MONE2, ZERO2);
        layer96<2>(smem, WB_L2, biasK + 192, Abuf, lane, cL1, cL2, ONE2, MONE2, ZERO2);
        layer96<2>(smem, WB_L3, biasK + 288, Abuf, lane, cL1, cL2, ONE2, MONE2, ZERO2);
        layer96<2>(smem, WB_L4, biasK + 384, Abuf, lane, cL1, cL2, ONE2, MONE2, ZERO2);
        fc_stage(smem, biasK + 480, Abuf, lane, ONE2);

        // ---- coalesced f32 store ----
#pragma unroll
        for (int i = 0; i < 16; i++) {
            int p = lane + i * 32;
            int r = p >> 4, c4 = p & 15;
            long long grow = rowbase + r;
            if (grow < B)
                o4[grow * 16 + c4] = *(const float4*)(Abuf + r * AP + 16 * c4);
        }
        __syncwarp();
    }
}

// ---------------- launch ----------------
extern "C" void kernel_launch(void* const* d_in, const int* in_sizes, int n_in,
                              void* d_out, int out_size) {
    (void)n_in; (void)out_size;
    const float* x         = (const float*)d_in[0];
    const float* w_ih0     = (const float*)d_in[1];
    // d_in[2] = w_hh0      (unused: h0 == 0, T == 1)
    const float* w_ih_rest = (const float*)d_in[3];
    // d_in[4] = w_hh_rest  (unused)
    const float* b_ih      = (const float*)d_in[5];
    const float* b_hh      = (const float*)d_in[6];
    const float* fc_w      = (const float*)d_in[7];
    const float* fc_b      = (const float*)d_in[8];
    float* out = (float*)d_out;

    int B = in_sizes[0] / 64;

    _LSTM_pack<<<(40960 + 544 + 255) / 256, 256>>>(
        w_ih0, w_ih_rest, b_ih, b_hh, fc_w, fc_b);

    cudaFuncSetAttribute(_LSTM_main,
                         cudaFuncAttributeMaxDynamicSharedMemorySize, SMEM_BYTES);
    int npair = (B + 511) / 512;
    int grid = npair < GRID ? npair : GRID;
    _LSTM_main<<<grid, NT, SMEM_BYTES>>>(x, out, B);
}

// round 11
// speedup vs baseline: 1.8950x; 1.5971x over previous
#include <cuda_runtime.h>
#include <cuda_fp16.h>
#include <cstdint>

// ============================================================================
// T=1, h0=c0=0 => w_hh* unused, f-gate unused. Chain of small GEMMs on HMMA
// (mma.sync m16n8k16 fp16 -> f32 accum).
// R10 precision scheme (kept): W = W_hi + W_lo fp16 (exact to 2^-22),
//   A = fp16(x); 2 MMA passes give A*W exactly; only A-quantization dropped.
// R11: epilogue via tanh.approx.f32 (MUFU.TANH):
//   sig(x) = 0.5*tanh(x/2)+0.5  =>  4 MUFU + ~7 FMA per h
//   (was 6 MUFU + ~14 packed FMA + mov churn). Biases for i,o pre-scaled 0.5.
// Persistent: 148 CTAs x 512 thr; warp owns 32 rows, warp-private A smem.
// ============================================================================

#define NT    512
#define GRID  148
#define AP    272
#define WIMG  84096
#define WARP_ABUF (32 * AP)
#define SMEM_BYTES (WIMG + 16 * WARP_ABUF)

// stage bases (bytes); per LSTM stage: [IG groups][O frags], hi then lo kidx
#define WB_L0 0
#define WB_L1 24576
#define WB_L2 36864
#define WB_L3 49152
#define WB_L4 61440
#define WB_FC 73728
#define BIAS_OFF 81920

__device__ __align__(16) unsigned char g_img[WIMG];

// ---------------- fast math ----------------
__device__ __forceinline__ float tanhap(float x) {
    float y; asm("tanh.approx.f32 %0, %1;" : "=f"(y) : "f"(x)); return y;
}
__device__ __forceinline__ uint32_t packh2(float a, float b) {
    __half2 v = __float22half2_rn(make_float2(a, b));
    return *reinterpret_cast<uint32_t*>(&v);
}

// fused LSTM activation: h = sig(o)*tanh(sig(i)*tanh(g)).
// bi,bo arrive pre-scaled by 0.5; bg plain.
__device__ __forceinline__ float act_h(float ci, float cg, float co,
                                       float bi, float bg, float bo) {
    float si = fmaf(tanhap(fmaf(ci, 0.5f, bi)), 0.5f, 0.5f);
    float tg = tanhap(cg + bg);
    float tc = tanhap(si * tg);
    float so = fmaf(tanhap(fmaf(co, 0.5f, bo)), 0.5f, 0.5f);
    return so * tc;
}

// ---------------- mma (fp16 inputs, f32 accum) ----------------
__device__ __forceinline__ void mma_f16(float c[4],
    const uint32_t a[4], uint32_t b0, uint32_t b1) {
    asm volatile(
        "mma.sync.aligned.m16n8k16.row.col.f32.f16.f16.f32 "
        "{%0,%1,%2,%3},{%4,%5,%6,%7},{%8,%9},{%0,%1,%2,%3};"
        : "+f"(c[0]), "+f"(c[1]), "+f"(c[2]), "+f"(c[3])
        : "r"(a[0]), "r"(a[1]), "r"(a[2]), "r"(a[3]), "r"(b0), "r"(b1));
}

// ---------------- weight pack: v2 layout, fp16 hi/lo (R10) ----------------
// LSTM stage s (KH = 4 for L0 else 2): kidx 0..2KH-1 (hi then lo) x 4 ntj.
//   IG group (kidx,ntj) at base + (kidx*4+ntj)*512: per lane 16B = i0,i1,g0,g1
//   O frag at base + KH*4096 + (kidx*4+ntj)*256: per lane 8B = o0,o1
// FC: kidx 0..3 (2 hi, 2 lo) x 8 ntj paired:
//   base + (kidx*4 + ntj/2)*512 + lane*16 + (ntj&1)*8
// Biases: i,o rows pre-scaled by 0.5 (for sig via tanh); g rows plain.
__global__ void _LSTM_pack(const float* __restrict__ w_ih0,
                           const float* __restrict__ w_ih_rest,
                           const float* __restrict__ b_ih,
                           const float* __restrict__ b_hh,
                           const float* __restrict__ fc_w,
                           const float* __restrict__ fc_b) {
    int i = blockIdx.x * blockDim.x + threadIdx.x;
    if (i < 40960) {
        int s, q;
        if (i < 12288)       { s = 0; q = i; }
        else if (i < 36864)  { s = 1 + (i - 12288) / 6144; q = (i - 12288) % 6144; }
        else                 { s = 5; q = i - 36864; }
        int fid = q >> 7, r = q & 127;
        int lane = r >> 2, reg = (r >> 1) & 1, half = r & 1;
        int n = lane >> 2;
        int kel = (lane & 3) * 2 + half + reg * 8;
        float w; unsigned dst;
        if (s < 5) {
            const int KH = (s == 0) ? 4 : 2;
            const unsigned base =
                (s == 0) ? 0u : (unsigned)(24576 + (s - 1) * 12288);
            int kidx = fid / 12, nt = fid % 12;
            int gate = nt >> 2, ntj = nt & 3;
            int is_lo = kidx >= KH;
            int k = (is_lo ? kidx - KH : kidx) * 16 + kel;
            int j = gate * 32 + ntj * 8 + n;
            int rr = (j < 32) ? j : j + 32;
            if (s == 0) w = w_ih0[rr * 64 + k];
            else        w = w_ih_rest[(s - 1) * 4096 + rr * 32 + k];
            __half hi = __float2half_rn(w);
            __half v = is_lo ? __float2half_rn(w - __half2float(hi)) : hi;
            if (gate < 2)
                dst = base + (unsigned)(kidx * 4 + ntj) * 512
                    + lane * 16 + gate * 8 + reg * 4 + half * 2;
            else
                dst = base + (unsigned)KH * 4096 + (unsigned)(kidx * 4 + ntj) * 256
                    + lane * 8 + reg * 4 + half * 2;
            *(__half*)(g_img + dst) = v;
        } else {
            int kidx = fid / 8, nt = fid % 8;   // fid 0..31
            int is_lo = kidx >= 2;
            int k = (is_lo ? kidx - 2 : kidx) * 16 + kel;
            int j = nt * 8 + n;
            w = fc_w[j * 32 + k];
            __half hi = __float2half_rn(w);
            __half v = is_lo ? __float2half_rn(w - __half2float(hi)) : hi;
            dst = WB_FC + (unsigned)(kidx * 4 + (nt >> 1)) * 512
                + lane * 16 + (nt & 1) * 8 + reg * 4 + half * 2;
            *(__half*)(g_img + dst) = v;
        }
    } else if (i < 40960 + 544) {
        int b = i - 40960; float v;
        if (b < 480) {
            int l = b / 96, j = b % 96;
            int rr = (j < 32) ? j : j + 32;
            v = b_ih[l * 128 + rr] + b_hh[l * 128 + rr];
            if (j < 32 || j >= 64) v *= 0.5f;   // i,o rows: sig via tanh(x/2)
        } else v = fc_b[b - 480];
        *(float*)(g_img + BIAS_OFF + b * 4) = v;
    }
}

// -------- one 96-col LSTM layer: A fully in regs, in-place h --------
template<int KH>
__device__ __forceinline__ void layer96(
    const unsigned char* __restrict__ wimg, uint32_t wbase,
    const float* __restrict__ biasK, unsigned char* __restrict__ Abuf,
    int lane)
{
    const int g = lane >> 2, q4 = lane & 3;
    uint32_t Ah[2][KH][4];
#pragma unroll
    for (int m = 0; m < 2; m++)
#pragma unroll
        for (int tk = 0; tk < KH; tk++) {
            const unsigned char* ab =
                Abuf + (m * 16 + g) * AP + 32 * tk + 4 * q4;
            Ah[m][tk][0] = *(const uint32_t*)ab;
            Ah[m][tk][1] = *(const uint32_t*)(ab + 8 * AP);
            Ah[m][tk][2] = *(const uint32_t*)(ab + 16);
            Ah[m][tk][3] = *(const uint32_t*)(ab + 8 * AP + 16);
        }
    __syncwarp();   // all lanes' A in regs before any h writes below

    const unsigned char* wIG = wimg + wbase + lane * 16;
    const unsigned char* wO  = wimg + wbase + KH * 4096 + lane * 8;

#pragma unroll
    for (int ntj = 0; ntj < 4; ntj++) {
        const unsigned char* aIG = wIG + ntj * 512;
        const unsigned char* aO  = wO  + ntj * 256;
        float Ci[2][4], Cg[2][4], Co[2][4];
#pragma unroll
        for (int m = 0; m < 2; m++)
#pragma unroll
            for (int q = 0; q < 4; q++) {
                Ci[m][q] = 0.f; Cg[m][q] = 0.f; Co[m][q] = 0.f;
            }
#pragma unroll
        for (int t = 0; t < 2 * KH; t++) {       // kidx = t (W hi then W lo)
            const int tk = t & (KH - 1);         // A reused for both segments
            uint4 igf = *(const uint4*)(aIG + t * 2048);
            uint2 of  = *(const uint2*)(aO  + t * 1024);
#pragma unroll
            for (int m = 0; m < 2; m++) {
                mma_f16(Ci[m], Ah[m][tk], igf.x, igf.y);
                mma_f16(Cg[m], Ah[m][tk], igf.z, igf.w);
                mma_f16(Co[m], Ah[m][tk], of.x,  of.y);
            }
        }
        const int col = ntj * 8 + q4 * 2;
        const float bi0 = biasK[col],      bi1 = biasK[col + 1];
        const float bg0 = biasK[32 + col], bg1 = biasK[33 + col];
        const float bo0 = biasK[64 + col], bo1 = biasK[65 + col];
#pragma unroll
        for (int m = 0; m < 2; m++) {
            float h0 = act_h(Ci[m][0], Cg[m][0], Co[m][0], bi0, bg0, bo0);
            float h1 = act_h(Ci[m][1], Cg[m][1], Co[m][1], bi1, bg1, bo1);
            float h2 = act_h(Ci[m][2], Cg[m][2], Co[m][2], bi0, bg0, bo0);
            float h3 = act_h(Ci[m][3], Cg[m][3], Co[m][3], bi1, bg1, bo1);
            unsigned char* r0 =
                Abuf + (m * 16 + g) * AP + 4 * (ntj * 4 + q4);
            *(uint32_t*)r0            = packh2(h0, h1);
            *(uint32_t*)(r0 + 8 * AP) = packh2(h2, h3);
        }
    }
    __syncwarp();
}

// -------- fc: A in regs; paired-ntj LDS.128 weights; f32 out staged --------
__device__ __forceinline__ void fc_stage(
    const unsigned char* __restrict__ wimg,
    const float* __restrict__ fb, unsigned char* __restrict__ Abuf, int lane)
{
    const int g = lane >> 2, q4 = lane & 3;
    uint32_t Ah[2][2][4];
#pragma unroll
    for (int m = 0; m < 2; m++)
#pragma unroll
        for (int tk = 0; tk < 2; tk++) {
            const unsigned char* ab =
                Abuf + (m * 16 + g) * AP + 32 * tk + 4 * q4;
            Ah[m][tk][0] = *(const uint32_t*)ab;
            Ah[m][tk][1] = *(const uint32_t*)(ab + 8 * AP);
            Ah[m][tk][2] = *(const uint32_t*)(ab + 16);
            Ah[m][tk][3] = *(const uint32_t*)(ab + 8 * AP + 16);
        }
    __syncwarp();

    const unsigned char* wp = wimg + WB_FC + lane * 16;

#pragma unroll
    for (int np = 0; np < 4; np++) {           // ntj pairs (2np, 2np+1)
        float C0[2][4], C1[2][4];
#pragma unroll
        for (int m = 0; m < 2; m++)
#pragma unroll
            for (int q = 0; q < 4; q++) { C0[m][q] = 0.f; C1[m][q] = 0.f; }
#pragma unroll
        for (int t = 0; t < 4; t++) {          // kidx = t (2 hi, 2 lo)
            const int tk = t & 1;
            uint4 bf = *(const uint4*)(wp + (uint32_t)(t * 4 + np) * 512);
#pragma unroll
            for (int m = 0; m < 2; m++) {
                mma_f16(C0[m], Ah[m][tk], bf.x, bf.y);
                mma_f16(C1[m], Ah[m][tk], bf.z, bf.w);
            }
        }
#pragma unroll
        for (int half = 0; half < 2; half++) {
            float (*C)[4] = half ? C1 : C0;
            const int col = (np * 2 + half) * 8 + q4 * 2;
            const float b0 = fb[col], b1 = fb[col + 1];
#pragma unroll
            for (int m = 0; m < 2; m++) {
                float* r0 = (float*)(Abuf + (m * 16 + g) * AP + 4 * col);
                float* r1 = (float*)((unsigned char*)r0 + 8 * AP);
                r0[0] = C[m][0] + b0; r0[1] = C[m][1] + b1;
                r1[0] = C[m][2] + b0; r1[1] = C[m][3] + b1;
            }
        }
    }
    __syncwarp();
}

// ---------------- main persistent kernel ----------------
__global__ void __launch_bounds__(NT, 1)
_LSTM_main(const float* __restrict__ x, float* __restrict__ out, int B) {
    extern __shared__ unsigned char smem[];
    const int tid = threadIdx.x;
    const int wid = tid >> 5;
    const int lane = tid & 31;

#pragma unroll 4
    for (int p = tid; p < WIMG / 16; p += NT)
        ((uint4*)smem)[p] = ((const uint4*)g_img)[p];
    __syncthreads();

    unsigned char* Abuf = smem + WIMG + wid * WARP_ABUF;
    const float* biasK = (const float*)(smem + BIAS_OFF);
    const float4* x4 = (const float4*)x;
    float4* o4 = (float4*)out;

    const int npair = (B + 511) >> 9;

#pragma unroll 1
    for (int it = blockIdx.x; it < npair; it += GRID) {
        const long long rowbase = (long long)it * 512 + wid * 32;

        // ---- load 32 x-rows, convert to fp16, stage (row = 128B) ----
#pragma unroll
        for (int i = 0; i < 16; i++) {
            int p = lane + i * 32;
            int r = p >> 4, c4 = p & 15;
            long long grow = rowbase + r;
            float4 v = (grow < B) ? x4[grow * 16 + c4]
                                  : make_float4(0.f, 0.f, 0.f, 0.f);
            uint32_t h0 = packh2(v.x, v.y), h1 = packh2(v.z, v.w);
            *(uint2*)(Abuf + r * AP + 8 * c4) = make_uint2(h0, h1);
        }
        __syncwarp();

        // ---- 5 LSTM layers (in-place, A in regs) + fc ----
        layer96<4>(smem, WB_L0, biasK,       Abuf, lane);
        layer96<2>(smem, WB_L1, biasK + 96,  Abuf, lane);
        layer96<2>(smem, WB_L2, biasK + 192, Abuf, lane);
        layer96<2>(smem, WB_L3, biasK + 288, Abuf, lane);
        layer96<2>(smem, WB_L4, biasK + 384, Abuf, lane);
        fc_stage(smem, biasK + 480, Abuf, lane);

        // ---- coalesced f32 store ----
#pragma unroll
        for (int i = 0; i < 16; i++) {
            int p = lane + i * 32;
            int r = p >> 4, c4 = p & 15;
            long long grow = rowbase + r;
            if (grow < B)
                o4[grow * 16 + c4] = *(const float4*)(Abuf + r * AP + 16 * c4);
        }
        __syncwarp();
    }
}

// ---------------- launch ----------------
extern "C" void kernel_launch(void* const* d_in, const int* in_sizes, int n_in,
                              void* d_out, int out_size) {
    (void)n_in; (void)out_size;
    const float* x         = (const float*)d_in[0];
    const float* w_ih0     = (const float*)d_in[1];
    // d_in[2] = w_hh0      (unused: h0 == 0, T == 1)
    const float* w_ih_rest = (const float*)d_in[3];
    // d_in[4] = w_hh_rest  (unused)
    const float* b_ih      = (const float*)d_in[5];
    const float* b_hh      = (const float*)d_in[6];
    const float* fc_w      = (const float*)d_in[7];
    const float* fc_b      = (const float*)d_in[8];
    float* out = (float*)d_out;

    int B = in_sizes[0] / 64;

    _LSTM_pack<<<(40960 + 544 + 255) / 256, 256>>>(
        w_ih0, w_ih_rest, b_ih, b_hh, fc_w, fc_b);

    cudaFuncSetAttribute(_LSTM_main,
                         cudaFuncAttributeMaxDynamicSharedMemorySize, SMEM_BYTES);
    int npair = (B + 511) / 512;
    int grid = npair < GRID ? npair : GRID;
    _LSTM_main<<<grid, NT, SMEM_BYTES>>>(x, out, B);
}